// round 17
// baseline (speedup 1.0000x reference)
#include <cuda_runtime.h>
#include <stdint.h>

// Problem shapes (fixed by the dataset).
#define BB 64
#define PP 2048
#define GG 512
#define NZ 16
#define GH (GG / NZ)                 // 32 gts per tile
#define BLK_PER_IMG (NZ * (PP / 512))  // 64 blocks per image

// Merged best per (image, pred): (iou_bits<<32) | (511 - g). Zero-initialized;
// phase A (last block per image) resets after consuming (replay-safe).
__device__ unsigned long long g_best[BB * PP];
__device__ float g_ap[BB];
__device__ unsigned int g_ticket_img[BB];  // per-image tickets (wrap 63->0)
__device__ unsigned int g_ticket;          // global mean ticket (wrap 63->0)

// ---------------------------------------------------------------------------
// Single fused kernel. grid = (PP/512, BB, NZ), 256 threads.
//
// K1 part (every block): per (image, pred, gt-tile) first-max argmax_g IoU +
// exact max value, merged via u64 atomicMax (iou desc, tie -> lower g).
//
// Tail (last-arriving block per image, via wrap-reset ticket):
//  Phase A: consume g_best (+reset). For each candidate (iou>0.5 & class
//    match), smem-atomicMax its key (score_bits<<32)|(1<<12)|(2047-p) into
//    sgt[g]. Winner per gt == reference's first-in-sorted-order TP
//    (score desc, tie -> lower p). Also cache all score bits in smem.
//  Phase B: per matched gt: j = 1 + #(winner keys greater) [O(m) smem scan];
//    k = 1 + global rank of winner (warp-cooperative uint4 scan of scores;
//    scores >= 0 so uint compare == float compare). AP term accumulated
//    deterministically; global ticket computes the batch mean.
// ---------------------------------------------------------------------------
__global__ __launch_bounds__(256, 6) void k_map(
    const float* __restrict__ pred_boxes,   // [B,P,4] xywh
    const float* __restrict__ gt_boxes,     // [B,G,4] xywh
    const float* __restrict__ pred_scores,  // [B,P]
    const int*   __restrict__ pred_classes, // [B,P]
    const int*   __restrict__ gt_classes,   // [B,G]
    float* __restrict__ out)
{
    const int b   = blockIdx.y;
    const int zt  = blockIdx.z;
    const int tid = threadIdx.x;
    const int p0  = blockIdx.x * 512 + tid;
    const int p1  = p0 + 256;

    __shared__ float4 sbox[GH];    // gt x1,y1,x2,y2
    __shared__ float  sarea[GH];   // gt area
    __shared__ unsigned int       sbits[PP];  // tail: raw score bits
    __shared__ unsigned long long sgt[GG];    // tail: per-gt winner key
    __shared__ float wred[8];
    __shared__ int   slast;

    // ---- K1: IoU argmax over this block's 32-gt tile ----
    const float4* gbp = reinterpret_cast<const float4*>(
        gt_boxes + ((size_t)b * GG + (size_t)zt * GH) * 4);
    if (tid < GH) {
        float4 v = gbp[tid];
        float x2 = v.x + v.z;
        float y2 = v.y + v.w;
        sbox[tid]  = make_float4(v.x, v.y, x2, y2);
        sarea[tid] = fabsf((x2 - v.x) * (y2 - v.y));
    }
    __syncthreads();

    const float4* pbp = reinterpret_cast<const float4*>(pred_boxes + (size_t)b * PP * 4);
    float4 q0 = pbp[p0];
    float4 q1 = pbp[p1];
    const float ax1 = q0.x, ay1 = q0.y, ax2 = q0.x + q0.z, ay2 = q0.y + q0.w;
    const float bx1 = q1.x, by1 = q1.y, bx2 = q1.x + q1.z, by2 = q1.y + q1.w;
    const float apa = fabsf((ax2 - ax1) * (ay2 - ay1)) + 1e-9f;  // area + eps hoisted
    const float bpa = fabsf((bx2 - bx1) * (by2 - by1)) + 1e-9f;

    float best0 = 0.0f, best1 = 0.0f;
    int   bg0 = 0, bg1 = 0;

#pragma unroll
    for (int g = 0; g < GH; ++g) {
        float4 gb = sbox[g];
        float  sa = sarea[g];
        {
            float iw = fminf(ax2, gb.z) - fmaxf(ax1, gb.x);   // unclamped
            float ih = fmaxf(fminf(ay2, gb.w) - fmaxf(ay1, gb.y), 0.0f);
            float n  = iw * ih;
            float u  = (apa + sa) - n;                        // >= eps, NaN-free
            float iou = __fdividef(n, u);
            if (iou > best0) { best0 = iou; bg0 = g; }        // strict > = first max
        }
        {
            float iw = fminf(bx2, gb.z) - fmaxf(bx1, gb.x);
            float ih = fmaxf(fminf(by2, gb.w) - fmaxf(by1, gb.y), 0.0f);
            float n  = iw * ih;
            float u  = (bpa + sa) - n;
            float iou = __fdividef(n, u);
            if (iou > best1) { best1 = iou; bg1 = g; }
        }
    }

    const int goff = zt * GH;
    atomicMax(&g_best[(size_t)b * PP + p0],
              ((unsigned long long)__float_as_uint(best0) << 32)
              | (unsigned)(511 - (bg0 + goff)));
    atomicMax(&g_best[(size_t)b * PP + p1],
              ((unsigned long long)__float_as_uint(best1) << 32)
              | (unsigned)(511 - (bg1 + goff)));

    // ---- Handoff: last block of this image runs the AP tail ----
    __threadfence();
    __syncthreads();
    if (tid == 0) {
        unsigned old = atomicInc(&g_ticket_img[b], BLK_PER_IMG - 1);  // wraps 63->0
        slast = (old == BLK_PER_IMG - 1) ? 1 : 0;
    }
    __syncthreads();
    if (!slast) return;

    // ---- Phase A: per-gt winner keys ----
    sgt[tid] = 0ULL;
    sgt[tid + 256] = 0ULL;
    __syncthreads();

#pragma unroll
    for (int k = 0; k < 8; ++k) {
        const int p = tid + k * 256;
        const size_t idx = (size_t)b * PP + p;
        unsigned long long v = g_best[idx];
        g_best[idx] = 0ULL;   // reset for next replay (sole reader)

        const int   ginv = (int)(v & 0x1FF);
        const int   g    = 511 - ginv;
        const float biou = __uint_as_float((unsigned int)(v >> 32));
        const unsigned sb = __float_as_uint(pred_scores[idx]);
        sbits[p] = sb;
        const bool cand = (biou > 0.5f) &&
                          (pred_classes[idx] == gt_classes[(size_t)b * GG + g]);
        if (cand)
            atomicMax(&sgt[g], ((unsigned long long)sb << 32)
                               | (1u << 12) | (unsigned)(2047 - p));
    }
    __syncthreads();

    // ---- Phase B: AP from per-gt winners ----
    const int lane = tid & 31, wid = tid >> 5;
    const unsigned full = 0xFFFFFFFFu;
    float acc = 0.0f;
    const int gbase = wid * 64;   // each warp owns 64 gts

#pragma unroll
    for (int half = 0; half < 2; ++half) {
        unsigned long long key = sgt[gbase + half * 32 + lane];
        unsigned bal = __ballot_sync(full, key != 0ULL);
        while (bal) {
            int src = __ffs(bal) - 1;
            bal &= bal - 1;
            unsigned long long kk = __shfl_sync(full, key, src);

            // j - 1 = #(winner keys strictly greater) over all 512 gts.
            int cj = 0;
#pragma unroll
            for (int i = 0; i < GG / 32; ++i)
                cj += (sgt[lane + i * 32] > kk) ? 1 : 0;

            // global rank of winner: #(q: bits_q > sc || (bits_q == sc && q < pc))
            const unsigned sc = (unsigned)(kk >> 32);
            const int      pc = 2047 - (int)(kk & 0x7FF);
            int cr = 0;
            const uint4* s4 = reinterpret_cast<const uint4*>(sbits);
#pragma unroll
            for (int i = 0; i < PP / 128; ++i) {
                int   wi = lane + i * 32;
                uint4 w  = s4[wi];
                int   qb = wi * 4;
                cr += (w.x > sc) || (w.x == sc && qb + 0 < pc);
                cr += (w.y > sc) || (w.y == sc && qb + 1 < pc);
                cr += (w.z > sc) || (w.z == sc && qb + 2 < pc);
                cr += (w.w > sc) || (w.w == sc && qb + 3 < pc);
            }
            cj = __reduce_add_sync(full, cj);
            cr = __reduce_add_sync(full, cr);

            if (lane == src) {
                // tp at rank cr (0-based), k = cr+1, tp-count j = 1+cj:
                // term = 0.5*( j/k + (k==1 ? 1 : (j-1)/(k-1)) )
                float pj  = (float)(1 + cj);
                float kkf = (float)(cr + 1);
                float prev = (cr == 0) ? 1.0f : (pj - 1.0f) / (float)cr;
                acc += 0.5f * (pj / kkf + prev);
            }
        }
    }

    // Deterministic block reduce (fixed assignment + fixed tree).
    for (int o = 16; o > 0; o >>= 1) acc += __shfl_down_sync(full, acc, o);
    if (lane == 0) wred[wid] = acc;
    __syncthreads();
    if (tid == 0) {
        float u = 0.0f;
#pragma unroll
        for (int w = 0; w < 8; ++w) u += wred[w];
        g_ap[b] = u / (float)GG;

        // Global ticket: last image computes the mean (wraps 63 -> 0).
        __threadfence();
        unsigned old = atomicInc(&g_ticket, BB - 1);
        if (old == BB - 1) {
            float s = 0.0f;
#pragma unroll
            for (int i = 0; i < BB; ++i) s += g_ap[i];   // fixed order
            out[0] = s * (1.0f / (float)BB);
        }
    }
}

// ---------------------------------------------------------------------------
extern "C" void kernel_launch(void* const* d_in, const int* in_sizes, int n_in,
                              void* d_out, int out_size)
{
    const float* pred_boxes   = (const float*)d_in[0];
    const float* pred_scores  = (const float*)d_in[1];
    const int*   pred_classes = (const int*)d_in[2];
    const float* gt_boxes     = (const float*)d_in[3];
    const int*   gt_classes   = (const int*)d_in[4];
    float* out = (float*)d_out;

    dim3 g1(PP / 512, BB, NZ);
    k_map<<<g1, 256>>>(pred_boxes, gt_boxes, pred_scores,
                       pred_classes, gt_classes, out);
}